// round 9
// baseline (speedup 1.0000x reference)
#include <cuda_runtime.h>

#define NLVL   16
#define WIDTH  1000
#define PADW   (WIDTH + 4)     // w in [-2, 1001]
#define RPITCH 17              // float2 per row-slot: bank pair = 2(w+n) -> conflict-free
#define TPB    1024

typedef unsigned long long u64;
typedef unsigned int       u32;

// ---------------- packed f32x2 helpers ----------------
__device__ __forceinline__ u64 pk(float lo, float hi) {
    u64 r; asm("mov.b64 %0, {%1,%2};" : "=l"(r) : "f"(lo), "f"(hi)); return r;
}
__device__ __forceinline__ void upk(float& lo, float& hi, u64 v) {
    asm("mov.b64 {%0,%1}, %2;" : "=f"(lo), "=f"(hi) : "l"(v));
}
__device__ __forceinline__ u64 f2fma(u64 a, u64 b, u64 c) {
    u64 r; asm("fma.rn.f32x2 %0, %1, %2, %3;" : "=l"(r) : "l"(a), "l"(b), "l"(c)); return r;
}
__device__ __forceinline__ u64 f2add(u64 a, u64 b) {
    u64 r; asm("add.rn.f32x2 %0, %1, %2;" : "=l"(r) : "l"(a), "l"(b)); return r;
}
__device__ __forceinline__ u64 f2sub(u64 a, u64 b) {
    u64 r; asm("sub.rn.f32x2 %0, %1, %2;" : "=l"(r) : "l"(a), "l"(b)); return r;
}
__device__ __forceinline__ u64 f2mul(u64 a, u64 b) {
    u64 r; asm("mul.rn.f32x2 %0, %1, %2;" : "=l"(r) : "l"(a), "l"(b)); return r;
}
__device__ __forceinline__ u64 bc(float v) { return pk(v, v); }

__device__ __forceinline__ float hwsin(float r) {   // r in [-pi, pi]
    float s; asm("sin.approx.f32 %0, %1;" : "=f"(s) : "f"(r)); return s;
}

// turns-domain reduction: rt = a' - rint(a')  (exact), rr = 2*pi*rt
__device__ __forceinline__ u64 fracred(u64 a, u64 MAGIC, u64 TWOPI) {
    u64 kb = f2add(a, MAGIC);
    u64 k  = f2sub(kb, MAGIC);
    u64 rt = f2sub(a, k);          // exact, in [-0.5, 0.5] turns
    return f2mul(rt, TWOPI);       // radians for MUFU, 1 rounding (~2e-7)
}

__global__ __launch_bounds__(TPB, 1)
void trig_hash_kernel(const float* __restrict__ x,
                      const float* __restrict__ grids,
                      const float* __restrict__ G,
                      const float* __restrict__ H,
                      float2* __restrict__ out,
                      int n_pairs)     // (B/2)*16
{
    extern __shared__ float2 gsm[];    // [(w+2)*17 + n]

    // Stage grids (N,C,W) -> stride-17 padded smem. Zeros outside [0,W).
    for (int j = threadIdx.x; j < PADW * NLVL; j += TPB) {
        int n = j & (NLVL - 1);
        int w = (j >> 4) - 2;
        float c0 = 0.f, c1 = 0.f;
        if ((unsigned)w < (unsigned)WIDTH) {
            c0 = grids[(n * 2 + 0) * WIDTH + w];
            c1 = grids[(n * 2 + 1) * WIDTH + w];
        }
        gsm[(w + 2) * RPITCH + n] = make_float2(c0, c1);
    }
    __syncthreads();

    const int gtid   = blockIdx.x * TPB + threadIdx.x;
    const int stride = gridDim.x * TPB;       // multiple of 16
    const int n      = gtid & (NLVL - 1);

    // Per-level constants pre-scaled to TURNS (fold 1/2pi into G, H).
    const float S = 0.15915494309189535f;
    const u64 G00 = bc(G[  0 + n]*S), G01 = bc(G[ 16 + n]*S), G02 = bc(G[ 32 + n]*S);
    const u64 G10 = bc(G[ 48 + n]*S), G11 = bc(G[ 64 + n]*S), G12 = bc(G[ 80 + n]*S);
    const u64 G20 = bc(G[ 96 + n]*S), G21 = bc(G[112 + n]*S), G22 = bc(G[128 + n]*S);
    const u64 H0  = bc(H[  0 + n]*S), H1  = bc(H[ 16 + n]*S), H2  = bc(H[ 32 + n]*S);

    const u64 MAGIC = bc(12582912.0f);               // 1.5 * 2^23
    const u64 TWOPI = bc(6.2831853071795865f);

    const float MAG499 = 12583411.0f;                // 12582912 + 499, exact

    u32 smbase;
    asm("{ .reg .u64 t; cvta.to.shared.u64 t, %1; cvt.u32.u64 %0, t; }"
        : "=r"(smbase) : "l"(gsm));
    // tap0 byte addr = (base+1)*136 + 8n + smbase = bits(bb)*136 + addrc (mod 2^32)
    const u32 addrc = smbase + 136u + (u32)(n * 8) - 1262485504u * 136u;

    // ---- software pipeline: preload x for the first iteration ----
    float2 q0, q1, q2;
    {
        int p0 = (gtid < n_pairs) ? gtid : 0;
        const float2* xp = (const float2*)(x + 6 * (p0 >> 4));
        q0 = xp[0]; q1 = xp[1]; q2 = xp[2];
    }

    for (int p = gtid; p < n_pairs; p += stride) {
        // ---- prefetch next iteration's x ----
        int pn = p + stride;
        int gn = ((pn < n_pairs) ? pn : p) >> 4;
        const float2* xn = (const float2*)(x + 6 * gn);
        float2 r0 = xn[0], r1 = xn[1], r2 = xn[2];

        // current pair: samples 2g (A), 2g+1 (B)
        u64 X0 = pk(q0.x, q1.y);
        u64 X1 = pk(q0.y, q2.x);
        u64 X2 = pk(q1.x, q2.y);

        // a' in turns
        u64 a0 = f2fma(X0, G00, f2fma(X1, G10, f2fma(X2, G20, H0)));
        u64 a1 = f2fma(X0, G01, f2fma(X1, G11, f2fma(X2, G21, H1)));
        u64 a2 = f2fma(X0, G02, f2fma(X1, G12, f2fma(X2, G22, H2)));

        u64 rr0 = fracred(a0, MAGIC, TWOPI);
        u64 rr1 = fracred(a1, MAGIC, TWOPI);
        u64 rr2 = fracred(a2, MAGIC, TWOPI);
        float r0A, r0B, r1A, r1B, r2A, r2B;
        upk(r0A, r0B, rr0); upk(r1A, r1B, rr1); upk(r2A, r2B, rr2);

        float gxA = hwsin(r0A) * hwsin(r1A) * hwsin(r2A);
        float gxB = hwsin(r0B) * hwsin(r1B) * hwsin(r2B);

        // fused ix chain: ix = 500*gx + 499.5
        float bbA = fmaf(gxA, 500.0f, MAG499);        // MAGIC + floor(ix)
        float bbB = fmaf(gxB, 500.0f, MAG499);
        float xfA = bbA - 12582912.0f;                // float(base)
        float xfB = bbB - 12582912.0f;
        float tA  = fmaf(gxA, 500.0f, 499.5f - xfA);  // t = ix - base
        float tB  = fmaf(gxB, 500.0f, 499.5f - xfB);

        // ---- issue all 8 tap loads up front (stride-17 rows: 136 B apart) ----
        const u32 adA = __float_as_uint(bbA) * 136u + addrc;
        const u32 adB = __float_as_uint(bbB) * 136u + addrc;
        float a0x,a0y,a1x,a1y,a2x,a2y,a3x,a3y;
        float b0x,b0y,b1x,b1y,b2x,b2y,b3x,b3y;
        asm("ld.shared.v2.f32 {%0,%1},[%2];"     : "=f"(a0x), "=f"(a0y) : "r"(adA));
        asm("ld.shared.v2.f32 {%0,%1},[%2+136];" : "=f"(a1x), "=f"(a1y) : "r"(adA));
        asm("ld.shared.v2.f32 {%0,%1},[%2+272];" : "=f"(a2x), "=f"(a2y) : "r"(adA));
        asm("ld.shared.v2.f32 {%0,%1},[%2+408];" : "=f"(a3x), "=f"(a3y) : "r"(adA));
        asm("ld.shared.v2.f32 {%0,%1},[%2];"     : "=f"(b0x), "=f"(b0y) : "r"(adB));
        asm("ld.shared.v2.f32 {%0,%1},[%2+136];" : "=f"(b1x), "=f"(b1y) : "r"(adB));
        asm("ld.shared.v2.f32 {%0,%1},[%2+272];" : "=f"(b2x), "=f"(b2y) : "r"(adB));
        asm("ld.shared.v2.f32 {%0,%1},[%2+408];" : "=f"(b3x), "=f"(b3y) : "r"(adB));

        // ---- scalar cubic weights, immediate-form FFMA ----
        float paA = fmaf(-0.75f, tA, 1.5f);  paA = fmaf(paA, tA, -0.75f);
        float w0A = paA * tA;
        float pbA = fmaf(1.25f, tA, -2.25f);
        float w1A = fmaf(pbA * tA, tA, 1.0f);
        float pcA = fmaf(-1.25f, tA, 1.5f);  pcA = fmaf(pcA, tA, 0.75f);
        float w2A = pcA * tA;
        float pdA = fmaf(0.75f, tA, -0.75f);
        float w3A = pdA * tA * tA;

        float paB = fmaf(-0.75f, tB, 1.5f);  paB = fmaf(paB, tB, -0.75f);
        float w0B = paB * tB;
        float pbB = fmaf(1.25f, tB, -2.25f);
        float w1B = fmaf(pbB * tB, tB, 1.0f);
        float pcB = fmaf(-1.25f, tB, 1.5f);  pcB = fmaf(pcB, tB, 0.75f);
        float w2B = pcB * tB;
        float pdB = fmaf(0.75f, tB, -0.75f);
        float w3B = pdB * tB * tB;

        float accA0 = fmaf(a0x, w0A, fmaf(a1x, w1A, fmaf(a2x, w2A, a3x * w3A)));
        float accA1 = fmaf(a0y, w0A, fmaf(a1y, w1A, fmaf(a2y, w2A, a3y * w3A)));
        float accB0 = fmaf(b0x, w0B, fmaf(b1x, w1B, fmaf(b2x, w2B, b3x * w3B)));
        float accB1 = fmaf(b0y, w0B, fmaf(b1y, w1B, fmaf(b2y, w2B, b3y * w3B)));

        const int iA = 2 * p - n;             // out float2 index = s*16 + n
        out[iA]        = make_float2(accA0, accA1);
        out[iA + NLVL] = make_float2(accB0, accB1);

        // rotate pipeline
        q0 = r0; q1 = r1; q2 = r2;
    }
}

extern "C" void kernel_launch(void* const* d_in, const int* in_sizes, int n_in,
                              void* d_out, int out_size)
{
    const float* x     = (const float*)d_in[0];
    const float* grids = (const float*)d_in[1];
    const float* G     = (const float*)d_in[2];
    const float* H     = (const float*)d_in[3];
    (void)n_in; (void)out_size;

    const int B       = in_sizes[0] / 3;
    const int n_pairs = (B / 2) * NLVL;

    const int smem_bytes = PADW * RPITCH * (int)sizeof(float2);   // 136544

    cudaFuncSetAttribute(trig_hash_kernel,
                         cudaFuncAttributeMaxDynamicSharedMemorySize, smem_bytes);

    int sm_count = 148;
    cudaDeviceGetAttribute(&sm_count, cudaDevAttrMultiProcessorCount, 0);

    trig_hash_kernel<<<sm_count, TPB, smem_bytes>>>(
        x, grids, G, H, (float2*)d_out, n_pairs);
}

// round 10
// speedup vs baseline: 1.3226x; 1.3226x over previous
#include <cuda_runtime.h>

#define NLVL   16
#define WIDTH  1000
#define PADW   (WIDTH + 4)     // w in [-2, 1001]
#define TPB    1024

typedef unsigned long long u64;
typedef unsigned int       u32;

// ---------------- packed f32x2 helpers ----------------
__device__ __forceinline__ u64 pk(float lo, float hi) {
    u64 r; asm("mov.b64 %0, {%1,%2};" : "=l"(r) : "f"(lo), "f"(hi)); return r;
}
__device__ __forceinline__ void upk(float& lo, float& hi, u64 v) {
    asm("mov.b64 {%0,%1}, %2;" : "=f"(lo), "=f"(hi) : "l"(v));
}
__device__ __forceinline__ u64 f2fma(u64 a, u64 b, u64 c) {
    u64 r; asm("fma.rn.f32x2 %0, %1, %2, %3;" : "=l"(r) : "l"(a), "l"(b), "l"(c)); return r;
}
__device__ __forceinline__ u64 f2add(u64 a, u64 b) {
    u64 r; asm("add.rn.f32x2 %0, %1, %2;" : "=l"(r) : "l"(a), "l"(b)); return r;
}
__device__ __forceinline__ u64 f2sub(u64 a, u64 b) {
    u64 r; asm("sub.rn.f32x2 %0, %1, %2;" : "=l"(r) : "l"(a), "l"(b)); return r;
}
__device__ __forceinline__ u64 f2mul(u64 a, u64 b) {
    u64 r; asm("mul.rn.f32x2 %0, %1, %2;" : "=l"(r) : "l"(a), "l"(b)); return r;
}
__device__ __forceinline__ u64 bc(float v) { return pk(v, v); }

__device__ __forceinline__ float hwsin(float r) {   // r in [-pi, pi]
    float s; asm("sin.approx.f32 %0, %1;" : "=f"(s) : "f"(r)); return s;
}

// turns-domain reduction: rt = a' - rint(a')  (exact), rr = 2*pi*rt
__device__ __forceinline__ u64 fracred(u64 a, u64 MAGIC, u64 TWOPI) {
    u64 kb = f2add(a, MAGIC);
    u64 k  = f2sub(kb, MAGIC);
    u64 rt = f2sub(a, k);          // exact, in [-0.5, 0.5] turns
    return f2mul(rt, TWOPI);       // radians for MUFU, 1 rounding
}

__global__ __launch_bounds__(TPB, 1)
void trig_hash_kernel(const float* __restrict__ x,
                      const float* __restrict__ grids,
                      const float* __restrict__ G,
                      const float* __restrict__ H,
                      float2* __restrict__ out,
                      int n_pairs)     // (B/2)*16
{
    extern __shared__ float2 gsm[];    // [(w+2)*16 + n] : conflict-free under half-warp phasing

    // Stage grids (N,C,W) -> transposed padded smem. Zeros outside [0,W).
    for (int j = threadIdx.x; j < PADW * NLVL; j += TPB) {
        int n = j & (NLVL - 1);
        int w = (j >> 4) - 2;
        float c0 = 0.f, c1 = 0.f;
        if ((unsigned)w < (unsigned)WIDTH) {
            c0 = grids[(n * 2 + 0) * WIDTH + w];
            c1 = grids[(n * 2 + 1) * WIDTH + w];
        }
        gsm[j] = make_float2(c0, c1);
    }
    __syncthreads();

    const int gtid   = blockIdx.x * TPB + threadIdx.x;
    const int stride = gridDim.x * TPB;       // multiple of 16
    const int n      = gtid & (NLVL - 1);

    // Per-level constants pre-scaled to TURNS (fold 1/2pi into G, H).
    const float S = 0.15915494309189535f;
    const u64 G00 = bc(G[  0 + n]*S), G01 = bc(G[ 16 + n]*S), G02 = bc(G[ 32 + n]*S);
    const u64 G10 = bc(G[ 48 + n]*S), G11 = bc(G[ 64 + n]*S), G12 = bc(G[ 80 + n]*S);
    const u64 G20 = bc(G[ 96 + n]*S), G21 = bc(G[112 + n]*S), G22 = bc(G[128 + n]*S);
    const u64 H0  = bc(H[  0 + n]*S), H1  = bc(H[ 16 + n]*S), H2  = bc(H[ 32 + n]*S);

    const u64 MAGIC = bc(12582912.0f);               // 1.5 * 2^23
    const u64 TWOPI = bc(6.2831853071795865f);
    // packed weight constants
    const u64 ONEp  = bc(1.0f);
    const u64 C075p = bc(0.75f);
    const u64 C125p = bc(1.25f);

    const float MAG499 = 12583411.0f;                // 12582912 + 499, exact

    u32 smbase;
    asm("{ .reg .u64 t; cvta.to.shared.u64 t, %1; cvt.u32.u64 %0, t; }"
        : "=r"(smbase) : "l"(gsm));
    // addr(tap0) = bits(bb)*128 + addrc   (0x4B400000*128 mod 2^32 = 0xA0000000)
    const u32 addrc = smbase + 128u + (u32)(n * 8) - 0xA0000000u;

    // ---- software pipeline: preload x for the first iteration ----
    float2 q0, q1, q2;
    {
        int p0 = (gtid < n_pairs) ? gtid : 0;
        const float2* xp = (const float2*)(x + 6 * (p0 >> 4));
        q0 = xp[0]; q1 = xp[1]; q2 = xp[2];
    }

    for (int p = gtid; p < n_pairs; p += stride) {
        // ---- prefetch next iteration's x ----
        int pn = p + stride;
        int gn = ((pn < n_pairs) ? pn : p) >> 4;
        const float2* xn = (const float2*)(x + 6 * gn);
        float2 r0 = xn[0], r1 = xn[1], r2 = xn[2];

        // current pair: samples 2g (A), 2g+1 (B)
        u64 X0 = pk(q0.x, q1.y);
        u64 X1 = pk(q0.y, q2.x);
        u64 X2 = pk(q1.x, q2.y);

        // a' in turns
        u64 a0 = f2fma(X0, G00, f2fma(X1, G10, f2fma(X2, G20, H0)));
        u64 a1 = f2fma(X0, G01, f2fma(X1, G11, f2fma(X2, G21, H1)));
        u64 a2 = f2fma(X0, G02, f2fma(X1, G12, f2fma(X2, G22, H2)));

        u64 rr0 = fracred(a0, MAGIC, TWOPI);
        u64 rr1 = fracred(a1, MAGIC, TWOPI);
        u64 rr2 = fracred(a2, MAGIC, TWOPI);
        float r0A, r0B, r1A, r1B, r2A, r2B;
        upk(r0A, r0B, rr0); upk(r1A, r1B, rr1); upk(r2A, r2B, rr2);

        float gxA = hwsin(r0A) * hwsin(r1A) * hwsin(r2A);
        float gxB = hwsin(r0B) * hwsin(r1B) * hwsin(r2B);

        // fused ix chain: ix = 500*gx + 499.5
        float bbA = fmaf(gxA, 500.0f, MAG499);        // MAGIC + floor(ix)
        float bbB = fmaf(gxB, 500.0f, MAG499);
        float xfA = bbA - 12582912.0f;                // float(base)
        float xfB = bbB - 12582912.0f;
        float tA  = fmaf(gxA, 500.0f, 499.5f - xfA);  // t = ix - base
        float tB  = fmaf(gxB, 500.0f, 499.5f - xfB);

        // ---- issue all 8 tap loads up front (row pitch 128 B) ----
        const u32 adA = __float_as_uint(bbA) * 128u + addrc;
        const u32 adB = __float_as_uint(bbB) * 128u + addrc;
        float a0x,a0y,a1x,a1y,a2x,a2y,a3x,a3y;
        float b0x,b0y,b1x,b1y,b2x,b2y,b3x,b3y;
        asm("ld.shared.v2.f32 {%0,%1},[%2];"     : "=f"(a0x), "=f"(a0y) : "r"(adA));
        asm("ld.shared.v2.f32 {%0,%1},[%2+128];" : "=f"(a1x), "=f"(a1y) : "r"(adA));
        asm("ld.shared.v2.f32 {%0,%1},[%2+256];" : "=f"(a2x), "=f"(a2y) : "r"(adA));
        asm("ld.shared.v2.f32 {%0,%1},[%2+384];" : "=f"(a3x), "=f"(a3y) : "r"(adA));
        asm("ld.shared.v2.f32 {%0,%1},[%2];"     : "=f"(b0x), "=f"(b0y) : "r"(adB));
        asm("ld.shared.v2.f32 {%0,%1},[%2+128];" : "=f"(b1x), "=f"(b1y) : "r"(adB));
        asm("ld.shared.v2.f32 {%0,%1},[%2+256];" : "=f"(b2x), "=f"(b2y) : "r"(adB));
        asm("ld.shared.v2.f32 {%0,%1},[%2+384];" : "=f"(b3x), "=f"(b3y) : "r"(adB));

        // ---- packed cubic weights via u = t^2 - t factorization ----
        u64 tp  = pk(tA, tB);
        u64 tm1 = f2sub(tp, ONEp);         // t-1
        u64 u   = f2mul(tp, tm1);          // t^2 - t
        u64 v   = f2mul(C075p, u);         // 0.75u
        u64 W3  = f2mul(v, tp);            // 0.75t^3 - 0.75t^2
        u64 W0  = f2sub(v, W3);            // 0.75u(1-t) = -0.75t(t-1)^2
        u64 omt = f2sub(ONEp, tp);         // 1-t
        u64 z   = f2mul(u, tp);            // t^3 - t^2
        u64 h   = f2sub(omt, u);           // 1 - t - u
        u64 W1  = f2fma(C125p, z, h);      // 1.25t^3 - 2.25t^2 + 1
        u64 r_  = f2sub(ONEp, W0);
        r_      = f2sub(r_, W1);
        u64 W2  = f2sub(r_, W3);           // 1 - w0 - w1 - w3 (exact identity)

        float w0A,w0B,w1A,w1B,w2A,w2B,w3A,w3B;
        upk(w0A, w0B, W0); upk(w1A, w1B, W1);
        upk(w2A, w2B, W2); upk(w3A, w3B, W3);

        float accA0 = fmaf(a0x, w0A, fmaf(a1x, w1A, fmaf(a2x, w2A, a3x * w3A)));
        float accA1 = fmaf(a0y, w0A, fmaf(a1y, w1A, fmaf(a2y, w2A, a3y * w3A)));
        float accB0 = fmaf(b0x, w0B, fmaf(b1x, w1B, fmaf(b2x, w2B, b3x * w3B)));
        float accB1 = fmaf(b0y, w0B, fmaf(b1y, w1B, fmaf(b2y, w2B, b3y * w3B)));

        const int iA = 2 * p - n;             // out float2 index = s*16 + n
        out[iA]        = make_float2(accA0, accA1);
        out[iA + NLVL] = make_float2(accB0, accB1);

        // rotate pipeline
        q0 = r0; q1 = r1; q2 = r2;
    }
}

extern "C" void kernel_launch(void* const* d_in, const int* in_sizes, int n_in,
                              void* d_out, int out_size)
{
    const float* x     = (const float*)d_in[0];
    const float* grids = (const float*)d_in[1];
    const float* G     = (const float*)d_in[2];
    const float* H     = (const float*)d_in[3];
    (void)n_in; (void)out_size;

    const int B       = in_sizes[0] / 3;
    const int n_pairs = (B / 2) * NLVL;

    const int smem_bytes = PADW * NLVL * (int)sizeof(float2);   // 128512

    cudaFuncSetAttribute(trig_hash_kernel,
                         cudaFuncAttributeMaxDynamicSharedMemorySize, smem_bytes);

    int sm_count = 148;
    cudaDeviceGetAttribute(&sm_count, cudaDevAttrMultiProcessorCount, 0);

    trig_hash_kernel<<<sm_count, TPB, smem_bytes>>>(
        x, grids, G, H, (float2*)d_out, n_pairs);
}